// round 16
// baseline (speedup 1.0000x reference)
#include <cuda_runtime.h>
#include <cuda_bf16.h>
#include <math.h>

#define NNDIM 512
#define DDIM  128
#define MROWS (NNDIM*NNDIM)   // 262144 rows of (i,j)

// Scratch (device globals).
__device__ unsigned g_zln  [(size_t)MROWS*64];           // LN1(Z) bf16-pairs, [row][cp]
__device__ __nv_bfloat16 g_leftb [(size_t)DDIM*MROWS];   // [c][row] bf16
__device__ __nv_bfloat16 g_rightb[(size_t)DDIM*MROWS];   // [c][row] bf16
__device__ float    g_gate[(size_t)DDIM*MROWS];          // [c][row] f32
__device__ unsigned g_pb  [(size_t)DDIM*MROWS/2];        // p bf16-pairs, per-c [i][j/2]
__device__ unsigned g_wop [DDIM*DDIM];                   // W_op tf32 bits, [c][d]

__device__ __forceinline__ float sigmoidf_(float x) { return 1.0f / (1.0f + expf(-x)); }

__device__ __forceinline__ unsigned f2tf32(float x) {
    unsigned r; asm("cvt.rna.tf32.f32 %0, %1;" : "=r"(r) : "f"(x)); return r;
}
__device__ __forceinline__ unsigned packbf(float lo, float hi) {
    unsigned r; asm("cvt.rn.bf16x2.f32 %0, %1, %2;" : "=r"(r) : "f"(hi), "f"(lo)); return r;
}

__device__ __forceinline__ void mma_tf32(float c[4],
    unsigned a0, unsigned a1, unsigned a2, unsigned a3, unsigned b0, unsigned b1)
{
    asm volatile(
        "mma.sync.aligned.m16n8k8.row.col.f32.tf32.tf32.f32 "
        "{%0,%1,%2,%3}, {%4,%5,%6,%7}, {%8,%9}, {%0,%1,%2,%3};"
        : "+f"(c[0]), "+f"(c[1]), "+f"(c[2]), "+f"(c[3])
        : "r"(a0), "r"(a1), "r"(a2), "r"(a3), "r"(b0), "r"(b1));
}
__device__ __forceinline__ void mma_bf16(float c[4],
    unsigned a0, unsigned a1, unsigned a2, unsigned a3, unsigned b0, unsigned b1)
{
    asm volatile(
        "mma.sync.aligned.m16n8k16.row.col.f32.bf16.bf16.f32 "
        "{%0,%1,%2,%3}, {%4,%5,%6,%7}, {%8,%9}, {%0,%1,%2,%3};"
        : "+f"(c[0]), "+f"(c[1]), "+f"(c[2]), "+f"(c[3])
        : "r"(a0), "r"(a1), "r"(a2), "r"(a3), "r"(b0), "r"(b1));
}
__device__ __forceinline__ void ldsm_x4(unsigned& r0, unsigned& r1, unsigned& r2,
                                        unsigned& r3, unsigned addr)
{
    asm volatile("ldmatrix.sync.aligned.m8n8.x4.shared.b16 {%0,%1,%2,%3}, [%4];"
        : "=r"(r0), "=r"(r1), "=r"(r2), "=r"(r3) : "r"(addr));
}

__device__ __forceinline__ void cp16(void* smem_dst, const void* gsrc) {
    unsigned d = (unsigned)__cvta_generic_to_shared(smem_dst);
    asm volatile("cp.async.ca.shared.global [%0], [%1], 16;" :: "r"(d), "l"(gsrc));
}
__device__ __forceinline__ void cp_commit() { asm volatile("cp.async.commit_group;"); }
template<int N> __device__ __forceinline__ void cp_wait() {
    asm volatile("cp.async.wait_group %0;" :: "n"(N));
}

// ---------------------------------------------------------------------------
// Kernel 0: LN1(Z) -> g_zln (bf16 pairs, [row][cp]). Warp-per-row, no smem.
// Block 0 also converts W_op -> g_wop (tf32). (R14 pass, unchanged.)
// ---------------------------------------------------------------------------
extern "C" __global__ void __launch_bounds__(256)
ln1_kernel(const float* __restrict__ Z, const float* __restrict__ g1v,
           const float* __restrict__ b1v, const float* __restrict__ Wop)
{
    const int t = threadIdx.x, lane = t & 31, wid = t >> 5;

    if (blockIdx.x == 0) {
        for (int idx = t; idx < 128*128; idx += 256)
            g_wop[idx] = f2tf32(Wop[idx]);
    }

    const size_t row = (size_t)blockIdx.x * 8 + wid;
    const float4 v  = *(const float4*)&Z[row*128 + lane*4];
    const float4 gv = *(const float4*)&g1v[lane*4];
    const float4 bv = *(const float4*)&b1v[lane*4];

    float s  = v.x + v.y + v.z + v.w;
    float s2 = v.x*v.x + v.y*v.y + v.z*v.z + v.w*v.w;
    #pragma unroll
    for (int o = 16; o > 0; o >>= 1) {
        s  += __shfl_xor_sync(0xffffffffu, s,  o);
        s2 += __shfl_xor_sync(0xffffffffu, s2, o);
    }
    float mu = s * (1.f/128.f);
    float rs = rsqrtf(s2 * (1.f/128.f) - mu*mu + 1e-5f);

    float n0 = (v.x - mu) * rs * gv.x + bv.x;
    float n1 = (v.y - mu) * rs * gv.y + bv.y;
    float n2 = (v.z - mu) * rs * gv.z + bv.z;
    float n3 = (v.w - mu) * rs * gv.w + bv.w;

    uint2 o2 = make_uint2(packbf(n0, n1), packbf(n2, n3));
    *(uint2*)&g_zln[row*64 + lane*2] = o2;
}

// ---------------------------------------------------------------------------
// Kernel 1: persistent projections + gating, bf16 tensor cores.
// (R14 pass, unchanged: W n-major [128][68], W frags via ldmatrix.x4.)
// ---------------------------------------------------------------------------
extern "C" __global__ void __launch_bounds__(512)
proj_kernel(const float* __restrict__ mask,
            const float* __restrict__ Wlr, const float* __restrict__ blr,
            const float* __restrict__ Wg,  const float* __restrict__ bg,
            const float* __restrict__ Wog, const float* __restrict__ bog)
{
    extern __shared__ unsigned smu[];
    unsigned* W1 = smu;                 // [128 n][68 kp]
    unsigned* W2 = W1 + 128*68;         // [128 n][68 kp]
    unsigned* As = W2 + 128*68;         // [2][64 row][68 kp]
    float* bb1 = (float*)(As + 2*64*68);
    float* bb2 = bb1 + 128;

    const int t = threadIdx.x, bx = blockIdx.x;
    int cg, ms, stride;
    if      (bx < 120) { cg = 0; ms = bx;       stride = 120; }
    else if (bx < 240) { cg = 1; ms = bx - 120; stride = 120; }
    else               { cg = 2; ms = bx - 240; stride = 60;  }
    const bool dual = (cg < 2);

    if (dual) {
        int cb = cg * 128;
        for (int idx = t; idx < 64*128; idx += 512) {
            int kp = idx >> 7, j = idx & 127;
            W1[j*68 + kp] = packbf(Wlr[(2*kp)*256 + cb + j], Wlr[(2*kp+1)*256 + cb + j]);
            W2[j*68 + kp] = packbf(Wg [(2*kp)*256 + cb + j], Wg [(2*kp+1)*256 + cb + j]);
        }
        if (t < 128) { bb1[t] = blr[cg*128 + t]; bb2[t] = bg[cg*128 + t]; }
    } else {
        for (int idx = t; idx < 64*128; idx += 512) {
            int kp = idx >> 7, j = idx & 127;
            W1[j*68 + kp] = packbf(Wog[(2*kp)*128 + j], Wog[(2*kp+1)*128 + j]);
        }
        if (t < 128) bb1[t] = bog[t];
    }

    const int lane = t & 31, w = t >> 5;
    const int wm = w & 1, wn = w >> 1;      // 2 m-warps x 8 n-warps
    const int tig = lane & 3, grp = lane >> 2;

    const unsigned sAs = (unsigned)__cvta_generic_to_shared(As);
    const int rla = lane & 15;
    const int kca = (lane >> 4) * 4;
    const unsigned aoff0 = ((wm*32 + 0*16 + rla)*68 + kca) * 4;
    const unsigned aoff1 = ((wm*32 + 1*16 + rla)*68 + kca) * 4;
    const unsigned bufstride = 64*68*4;

    const unsigned sW1 = (unsigned)__cvta_generic_to_shared(W1);
    const unsigned sW2 = (unsigned)__cvta_generic_to_shared(W2);
    const int rlw = (lane & 7) + ((lane >> 4) << 3);
    const int kcw = ((lane >> 3) & 1) * 4;
    const unsigned woff = ((wn*16 + rlw)*68 + kcw) * 4;

    __nv_bfloat16* dstb = (cg == 0) ? g_leftb : g_rightb;

    int tile = ms;
    {
        int m0 = tile * 64;
        #pragma unroll
        for (int i = 0; i < 2; ++i) {
            int idx = t + 512*i;
            int r = idx >> 4, kq = idx & 15;
            cp16(As + r*68 + kq*4, g_zln + (size_t)(m0 + r)*64 + kq*4);
        }
        cp_commit();
    }
    int buf = 0;

    for (; tile < 4096; tile += stride) {
        int nxt = tile + stride;
        if (nxt < 4096) {
            int m0 = nxt * 64;
            unsigned* db = As + (buf^1)*64*68;
            #pragma unroll
            for (int i = 0; i < 2; ++i) {
                int idx = t + 512*i;
                int r = idx >> 4, kq = idx & 15;
                cp16(db + r*68 + kq*4, g_zln + (size_t)(m0 + r)*64 + kq*4);
            }
            cp_commit();
            cp_wait<1>();
        } else {
            cp_wait<0>();
        }
        __syncthreads();

        const unsigned abase = sAs + buf*bufstride;
        const int rb = tile * 64;

        float mpre[2][2];
        if (dual) {
            #pragma unroll
            for (int mt = 0; mt < 2; ++mt)
                #pragma unroll
                for (int h = 0; h < 2; ++h)
                    mpre[mt][h] = __ldg(&mask[rb + wm*32 + mt*16 + grp + h*8]);
        }

        float acc1[2][2][4], acc2[2][2][4];
        #pragma unroll
        for (int mt = 0; mt < 2; ++mt)
            #pragma unroll
            for (int nt = 0; nt < 2; ++nt)
                #pragma unroll
                for (int q = 0; q < 4; ++q) { acc1[mt][nt][q] = 0.f; acc2[mt][nt][q] = 0.f; }

        #pragma unroll
        for (int kp0 = 0; kp0 < 64; kp0 += 8) {
            unsigned af[2][4];
            ldsm_x4(af[0][0], af[0][1], af[0][2], af[0][3], abase + aoff0 + kp0*4);
            ldsm_x4(af[1][0], af[1][1], af[1][2], af[1][3], abase + aoff1 + kp0*4);
            unsigned bw1[4];
            ldsm_x4(bw1[0], bw1[1], bw1[2], bw1[3], sW1 + woff + kp0*4);
            if (dual) {
                unsigned bw2[4];
                ldsm_x4(bw2[0], bw2[1], bw2[2], bw2[3], sW2 + woff + kp0*4);
                mma_bf16(acc1[0][0], af[0][0], af[0][1], af[0][2], af[0][3], bw1[0], bw1[1]);
                mma_bf16(acc1[1][0], af[1][0], af[1][1], af[1][2], af[1][3], bw1[0], bw1[1]);
                mma_bf16(acc1[0][1], af[0][0], af[0][1], af[0][2], af[0][3], bw1[2], bw1[3]);
                mma_bf16(acc1[1][1], af[1][0], af[1][1], af[1][2], af[1][3], bw1[2], bw1[3]);
                mma_bf16(acc2[0][0], af[0][0], af[0][1], af[0][2], af[0][3], bw2[0], bw2[1]);
                mma_bf16(acc2[1][0], af[1][0], af[1][1], af[1][2], af[1][3], bw2[0], bw2[1]);
                mma_bf16(acc2[0][1], af[0][0], af[0][1], af[0][2], af[0][3], bw2[2], bw2[3]);
                mma_bf16(acc2[1][1], af[1][0], af[1][1], af[1][2], af[1][3], bw2[2], bw2[3]);
            } else {
                mma_bf16(acc1[0][0], af[0][0], af[0][1], af[0][2], af[0][3], bw1[0], bw1[1]);
                mma_bf16(acc1[1][0], af[1][0], af[1][1], af[1][2], af[1][3], bw1[0], bw1[1]);
                mma_bf16(acc1[0][1], af[0][0], af[0][1], af[0][2], af[0][3], bw1[2], bw1[3]);
                mma_bf16(acc1[1][1], af[1][0], af[1][1], af[1][2], af[1][3], bw1[2], bw1[3]);
            }
        }

        #pragma unroll
        for (int mt = 0; mt < 2; ++mt) {
            #pragma unroll
            for (int nt = 0; nt < 2; ++nt) {
                #pragma unroll
                for (int q = 0; q < 4; ++q) {
                    int r  = wm*32 + mt*16 + grp + ((q >= 2) ? 8 : 0);
                    int oc = wn*16 + nt*8 + tig*2 + (q & 1);
                    if (dual) {
                        float lrv = acc1[mt][nt][q] + bb1[oc];
                        float gtv = acc2[mt][nt][q] + bb2[oc];
                        dstb[(size_t)oc*MROWS + rb + r] =
                            __float2bfloat16(lrv * mpre[mt][q >= 2] * sigmoidf_(gtv));
                    } else {
                        g_gate[(size_t)oc*MROWS + rb + r] =
                            sigmoidf_(acc1[mt][nt][q] + bb1[oc]);
                    }
                }
            }
        }
        __syncthreads();
        buf ^= 1;
    }
}

// ---------------------------------------------------------------------------
// Kernel 2: p[c] = L_c @ R_c^T via bf16 mma, cp.async 2-stage BK=32, ldmatrix.
// (Byte-identical to the R10/R14 pass.)
// ---------------------------------------------------------------------------
extern "C" __global__ void __launch_bounds__(256, 2)
einsum_kernel()
{
    __shared__ unsigned As[2][128][20];
    __shared__ unsigned Bs[2][128][20];

    const int t = threadIdx.x;
    const int lane = t & 31;
    const int w = t >> 5;
    const int wm = w & 3;
    const int wn = w >> 2;
    const int jbase = blockIdx.x * 128;
    const int ibase = blockIdx.y * 128;
    const int c = blockIdx.z;

    const __nv_bfloat16* A = g_leftb  + (size_t)c*MROWS + (size_t)ibase*512;
    const __nv_bfloat16* B = g_rightb + (size_t)c*MROWS + (size_t)jbase*512;

    const int tig = lane & 3;
    const int grp = lane >> 2;

    const unsigned sAs = (unsigned)__cvta_generic_to_shared(As);
    const unsigned sBs = (unsigned)__cvta_generic_to_shared(Bs);
    const int rla = lane & 15;
    const int kca = (lane >> 4) * 4;
    const int rlb = (lane & 7) + ((lane >> 4) << 3);
    const int kcb = ((lane >> 3) & 1) * 4;
    unsigned aoff[2], boff[4];
    #pragma unroll
    for (int mt = 0; mt < 2; ++mt)
        aoff[mt] = ((wm*32 + mt*16 + rla)*20 + kca) * 4;
    #pragma unroll
    for (int ntp = 0; ntp < 4; ++ntp)
        boff[ntp] = ((wn*64 + ntp*16 + rlb)*20 + kcb) * 4;
    const unsigned ststride = 128*20*4;

    float acc[2][8][4];
    #pragma unroll
    for (int mt = 0; mt < 2; ++mt)
        #pragma unroll
        for (int nt = 0; nt < 8; ++nt)
            #pragma unroll
            for (int q = 0; q < 4; ++q) acc[mt][nt][q] = 0.f;

    #pragma unroll
    for (int st = 0; st < 2; ++st) {
        int k0 = st * 32;
        #pragma unroll
        for (int i = 0; i < 2; ++i) {
            int idx = t + 256*i;
            int row = idx >> 2, q = idx & 3;
            cp16(&As[st][row][q*4], A + row*512 + k0 + q*8);
            cp16(&Bs[st][row][q*4], B + row*512 + k0 + q*8);
        }
        cp_commit();
    }

    int it = 0;
    for (int k0 = 0; k0 < 512; k0 += 32, it ^= 1) {
        if (k0 + 32 >= 512) cp_wait<0>(); else cp_wait<1>();
        __syncthreads();

        const unsigned ab = sAs + it*ststride;
        const unsigned bb = sBs + it*ststride;

        #pragma unroll
        for (int kk = 0; kk < 2; ++kk) {
            unsigned af[2][4], bf[8][2];
            ldsm_x4(af[0][0], af[0][1], af[0][2], af[0][3], ab + aoff[0] + kk*32);
            ldsm_x4(af[1][0], af[1][1], af[1][2], af[1][3], ab + aoff[1] + kk*32);
            #pragma unroll
            for (int ntp = 0; ntp < 4; ++ntp)
                ldsm_x4(bf[ntp*2][0], bf[ntp*2][1], bf[ntp*2+1][0], bf[ntp*2+1][1],
                        bb + boff[ntp] + kk*32);
            #pragma unroll
            for (int mt = 0; mt < 2; ++mt)
                #pragma unroll
                for (int nt = 0; nt < 8; ++nt)
                    mma_bf16(acc[mt][nt], af[mt][0], af[mt][1], af[mt][2], af[mt][3],
                             bf[nt][0], bf[nt][1]);
        }

        if (k0 + 64 < 512) {
            __syncthreads();
            int kn = k0 + 64;
            #pragma unroll
            for (int i = 0; i < 2; ++i) {
                int idx = t + 256*i;
                int row = idx >> 2, q = idx & 3;
                cp16(&As[it][row][q*4], A + row*512 + kn + q*8);
                cp16(&Bs[it][row][q*4], B + row*512 + kn + q*8);
            }
            cp_commit();
        }
    }

    unsigned* Pb = g_pb + (size_t)c*(MROWS/2);
    #pragma unroll
    for (int mt = 0; mt < 2; ++mt) {
        int i0 = ibase + wm*32 + mt*16 + grp;
        #pragma unroll
        for (int nt = 0; nt < 8; ++nt) {
            int j0 = jbase + wn*64 + nt*8 + tig*2;
            Pb[(size_t)i0*256 + (j0 >> 1)]     = packbf(acc[mt][nt][0], acc[mt][nt][1]);
            Pb[(size_t)(i0+8)*256 + (j0 >> 1)] = packbf(acc[mt][nt][2], acc[mt][nt][3]);
        }
    }
}

// ---------------------------------------------------------------------------
// Kernel 3: PERSISTENT LN2 + (pln @ W_op, tf32) + gate + residual.
// CHANGE vs R14: 1024 threads (32 warps, 4m x 8n), same 64-row/2-stage
// structure, same math. All phases get 2x warp parallelism.
// ---------------------------------------------------------------------------
extern "C" __global__ void __launch_bounds__(1024)
final_kernel(const float* __restrict__ Z,
             const float* __restrict__ g2v, const float* __restrict__ b2v,
             const float* __restrict__ obias, float* __restrict__ out)
{
    extern __shared__ unsigned smu[];
    unsigned* Ws  = smu;                  // [128 c][136 d] tf32
    unsigned* Pu0 = Ws + 128*136;         // [128 c][72]: cols 32..63 packed on load
    unsigned* Pu1 = Pu0 + 128*72;
    float* ps1 = (float*)(Pu1 + 128*72);  // [16][64]
    float* ps2 = ps1 + 16*64;
    float* g2s = ps2 + 16*64;             // 128
    float* b2s = g2s + 128;
    float* obs = b2s + 128;
    float* mus = obs + 128;               // 64
    float* rss = mus + 64;                // 64

    const int t = threadIdx.x;

    // prologue: W_op + first P tile in one group
    #pragma unroll
    for (int i = 0; i < 4; ++i) {
        int idx = t + 1024*i;             // 0..4095
        int c = idx >> 5, seg = idx & 31;
        cp16(Ws + c*136 + seg*4, g_wop + c*128 + seg*4);
    }
    {
        int rb0 = blockIdx.x * 64;
        int c = t >> 3, seg = t & 7;      // 1024 cp16, one per thread
        cp16(Pu0 + c*72 + 32 + seg*4, g_pb + (size_t)c*(MROWS/2) + (rb0 >> 1) + seg*4);
    }
    cp_commit();
    if (t < 128) { g2s[t] = g2v[t]; b2s[t] = b2v[t]; obs[t] = obias[t]; }

    const int lane = t & 31, w = t >> 5;
    const int wm = w & 3, wn = w >> 2;    // 4 m-warps (16r) x 8 n-warps (16d)
    const int tig = lane & 3, grp = lane >> 2;

    int st = 0;
    for (int tile = blockIdx.x; tile < 4096; tile += 152, st ^= 1) {
        unsigned* Pu = st ? Pu1 : Pu0;
        const int rb = tile * 64;

        cp_wait<0>();
        __syncthreads();

        // prefetch NEXT tile's packed P into the other stage
        int ntile = tile + 152;
        if (ntile < 4096) {
            unsigned* D = st ? Pu0 : Pu1;
            int rbn = ntile * 64;
            int c = t >> 3, seg = t & 7;
            cp16(D + c*72 + 32 + seg*4, g_pb + (size_t)c*(MROWS/2) + (rbn >> 1) + seg*4);
            cp_commit();
        }

        // LN partials over c (16 groups of 8 c's, lanes sweep 64 rows)
        {
            int h = t >> 6, r = t & 63;
            int r2 = r >> 1, hi = r & 1;
            float s = 0.f, s2 = 0.f;
            #pragma unroll
            for (int cc = 0; cc < 8; ++cc) {
                unsigned pk = Pu[(h*8 + cc)*72 + 32 + r2];
                __nv_bfloat162 h2 = *reinterpret_cast<const __nv_bfloat162*>(&pk);
                float v = hi ? __bfloat162float(h2.y) : __bfloat162float(h2.x);
                s += v; s2 += v*v;
            }
            ps1[h*64 + r] = s; ps2[h*64 + r] = s2;
        }
        __syncthreads();
        if (t < 64) {
            float s = 0.f, s2 = 0.f;
            #pragma unroll
            for (int h = 0; h < 16; ++h) { s += ps1[h*64 + t]; s2 += ps2[h*64 + t]; }
            float mu = s * (1.f/128.f);
            float var = s2 * (1.f/128.f) - mu*mu;
            mus[t] = mu; rss[t] = rsqrtf(var + 1e-5f);
        }
        __syncthreads();

        // expand packed bf16 -> tf32 in place (register-staged)
        {
            unsigned pk[4];
            #pragma unroll
            for (int i = 0; i < 4; ++i) {
                int idx = t + 1024*i;         // 0..4095 pairs
                int c = idx >> 5, r2 = idx & 31;
                pk[i] = Pu[c*72 + 32 + r2];
            }
            __syncthreads();
            #pragma unroll
            for (int i = 0; i < 4; ++i) {
                int idx = t + 1024*i;
                int c = idx >> 5, r2 = idx & 31, r = r2*2;
                __nv_bfloat162 h2 = *reinterpret_cast<const __nv_bfloat162*>(&pk[i]);
                float vx = __bfloat162float(h2.x), vy = __bfloat162float(h2.y);
                Pu[c*72 + r    ] = f2tf32((vx - mus[r  ]) * rss[r  ] * g2s[c] + b2s[c]);
                Pu[c*72 + r + 1] = f2tf32((vy - mus[r+1]) * rss[r+1] * g2s[c] + b2s[c]);
            }
        }
        __syncthreads();

        // prefetch gate + Z (latency hidden under GEMM)
        float  gpre[2][4];
        float2 zpre[2][2];
        #pragma unroll
        for (int nt = 0; nt < 2; ++nt) {
            int d0 = wn*16 + nt*8 + tig*2;
            int r0 = wm*16 + grp;
            #pragma unroll
            for (int q = 0; q < 4; ++q) {
                int r = r0 + ((q >= 2) ? 8 : 0);
                gpre[nt][q] = __ldg(&g_gate[(size_t)(d0 + (q & 1))*MROWS + rb + r]);
            }
            zpre[nt][0] = *(const float2*)&Z[(size_t)(rb + r0    )*128 + d0];
            zpre[nt][1] = *(const float2*)&Z[(size_t)(rb + r0 + 8)*128 + d0];
        }

        // GEMM: M=64(r), N=128(d), K=128(c); 32 warps = 4m x 8n, 2 n-tiles each
        float acc[2][4];
        #pragma unroll
        for (int nt = 0; nt < 2; ++nt)
            #pragma unroll
            for (int q = 0; q < 4; ++q) acc[nt][q] = 0.f;

        const int ar = wm*16 + grp;
        #pragma unroll
        for (int k0 = 0; k0 < 128; k0 += 8) {
            unsigned a0 = Pu[(k0+tig  )*72 + ar];
            unsigned a1 = Pu[(k0+tig  )*72 + ar + 8];
            unsigned a2 = Pu[(k0+tig+4)*72 + ar];
            unsigned a3 = Pu[(k0+tig+4)*72 + ar + 8];
            #pragma unroll
            for (int nt = 0; nt < 2; ++nt) {
                int bc = wn*16 + nt*8 + grp;
                unsigned b0 = Ws[(k0+tig)*136 + bc], b1 = Ws[(k0+tig+4)*136 + bc];
                mma_tf32(acc[nt], a0, a1, a2, a3, b0, b1);
            }
        }

        // epilogue: direct gated-residual float2 stores (sector-aligned)
        #pragma unroll
        for (int nt = 0; nt < 2; ++nt) {
            int d0 = wn*16 + nt*8 + tig*2;
            int r0 = wm*16 + grp;
            float ob0 = obs[d0], ob1 = obs[d0 + 1];
            float2 o0, o1;
            o0.x = zpre[nt][0].x + gpre[nt][0] * (acc[nt][0] + ob0);
            o0.y = zpre[nt][0].y + gpre[nt][1] * (acc[nt][1] + ob1);
            o1.x = zpre[nt][1].x + gpre[nt][2] * (acc[nt][2] + ob0);
            o1.y = zpre[nt][1].y + gpre[nt][3] * (acc[nt][3] + ob1);
            *(float2*)&out[(size_t)(rb + r0    )*128 + d0] = o0;
            *(float2*)&out[(size_t)(rb + r0 + 8)*128 + d0] = o1;
        }
        // next iteration's cp_wait + __syncthreads protects buffer reuse
    }
}

// ---------------------------------------------------------------------------
extern "C" void kernel_launch(void* const* d_in, const int* in_sizes, int n_in,
                              void* d_out, int out_size)
{
    const float* Zr   = (const float*)d_in[0];
    const float* mask = (const float*)d_in[1];
    const float* g1   = (const float*)d_in[2];
    const float* b1   = (const float*)d_in[3];
    const float* Wlr  = (const float*)d_in[4];
    const float* blr  = (const float*)d_in[5];
    const float* Wg   = (const float*)d_in[6];
    const float* bg   = (const float*)d_in[7];
    const float* Wog  = (const float*)d_in[8];
    const float* bog  = (const float*)d_in[9];
    const float* g2   = (const float*)d_in[10];
    const float* b2   = (const float*)d_in[11];
    const float* Wop  = (const float*)d_in[12];
    const float* ob   = (const float*)d_in[13];
    float* out = (float*)d_out;

    const size_t sm1 = (size_t)(2*128*68 + 2*64*68 + 256) * 4;                   // ~105.5 KB
    const size_t sm3 = (size_t)(128*136 + 2*128*72 + 32*64 + 3*128 + 2*64) * 4;  // ~153.6 KB
    cudaFuncSetAttribute(proj_kernel,  cudaFuncAttributeMaxDynamicSharedMemorySize, (int)sm1);
    cudaFuncSetAttribute(final_kernel, cudaFuncAttributeMaxDynamicSharedMemorySize, (int)sm3);

    ln1_kernel<<<32768, 256>>>(Zr, g1, b1, Wop);
    proj_kernel<<<300, 512, sm1>>>(mask, Wlr, blr, Wg, bg, Wog, bog);
    einsum_kernel<<<dim3(4, 4, 128), 256>>>();
    final_kernel<<<152, 1024, sm3>>>(Zr, g2, b2, ob, out);
}

// round 17
// speedup vs baseline: 1.1315x; 1.1315x over previous
#include <cuda_runtime.h>
#include <cuda_bf16.h>
#include <math.h>

#define NNDIM 512
#define DDIM  128
#define MROWS (NNDIM*NNDIM)   // 262144 rows of (i,j)

// Scratch (device globals).
__device__ unsigned g_zln  [(size_t)MROWS*64];           // LN1(Z) bf16-pairs, [row][cp]
__device__ __nv_bfloat16 g_leftb [(size_t)DDIM*MROWS];   // [c][row] bf16
__device__ __nv_bfloat16 g_rightb[(size_t)DDIM*MROWS];   // [c][row] bf16
__device__ float    g_gate[(size_t)DDIM*MROWS];          // [c][row] f32
__device__ unsigned g_pb  [(size_t)DDIM*MROWS/2];        // p bf16-pairs, per-c [i][j/2]
__device__ unsigned g_wopb[DDIM*64];                     // W_op bf16 c-pairs, n-major [d][cp]

__device__ __forceinline__ float sigmoidf_(float x) { return 1.0f / (1.0f + expf(-x)); }

__device__ __forceinline__ unsigned packbf(float lo, float hi) {
    unsigned r; asm("cvt.rn.bf16x2.f32 %0, %1, %2;" : "=r"(r) : "f"(hi), "f"(lo)); return r;
}

__device__ __forceinline__ void mma_bf16(float c[4],
    unsigned a0, unsigned a1, unsigned a2, unsigned a3, unsigned b0, unsigned b1)
{
    asm volatile(
        "mma.sync.aligned.m16n8k16.row.col.f32.bf16.bf16.f32 "
        "{%0,%1,%2,%3}, {%4,%5,%6,%7}, {%8,%9}, {%0,%1,%2,%3};"
        : "+f"(c[0]), "+f"(c[1]), "+f"(c[2]), "+f"(c[3])
        : "r"(a0), "r"(a1), "r"(a2), "r"(a3), "r"(b0), "r"(b1));
}
__device__ __forceinline__ void ldsm_x4(unsigned& r0, unsigned& r1, unsigned& r2,
                                        unsigned& r3, unsigned addr)
{
    asm volatile("ldmatrix.sync.aligned.m8n8.x4.shared.b16 {%0,%1,%2,%3}, [%4];"
        : "=r"(r0), "=r"(r1), "=r"(r2), "=r"(r3) : "r"(addr));
}

__device__ __forceinline__ void cp16(void* smem_dst, const void* gsrc) {
    unsigned d = (unsigned)__cvta_generic_to_shared(smem_dst);
    asm volatile("cp.async.ca.shared.global [%0], [%1], 16;" :: "r"(d), "l"(gsrc));
}
__device__ __forceinline__ void cp_commit() { asm volatile("cp.async.commit_group;"); }
template<int N> __device__ __forceinline__ void cp_wait() {
    asm volatile("cp.async.wait_group %0;" :: "n"(N));
}

// ---------------------------------------------------------------------------
// Kernel 0: LN1(Z) -> g_zln (bf16 pairs). Block 0 packs W_op -> g_wopb
// (bf16 c-pairs, n-major [d][cp]).
// ---------------------------------------------------------------------------
extern "C" __global__ void __launch_bounds__(256)
ln1_kernel(const float* __restrict__ Z, const float* __restrict__ g1v,
           const float* __restrict__ b1v, const float* __restrict__ Wop)
{
    const int t = threadIdx.x, lane = t & 31, wid = t >> 5;

    if (blockIdx.x == 0) {
        for (int idx = t; idx < 128*64; idx += 256) {
            int d = idx >> 6, cp = idx & 63;
            g_wopb[d*64 + cp] = packbf(Wop[(2*cp)*128 + d], Wop[(2*cp+1)*128 + d]);
        }
    }

    const size_t row = (size_t)blockIdx.x * 8 + wid;
    const float4 v  = *(const float4*)&Z[row*128 + lane*4];
    const float4 gv = *(const float4*)&g1v[lane*4];
    const float4 bv = *(const float4*)&b1v[lane*4];

    float s  = v.x + v.y + v.z + v.w;
    float s2 = v.x*v.x + v.y*v.y + v.z*v.z + v.w*v.w;
    #pragma unroll
    for (int o = 16; o > 0; o >>= 1) {
        s  += __shfl_xor_sync(0xffffffffu, s,  o);
        s2 += __shfl_xor_sync(0xffffffffu, s2, o);
    }
    float mu = s * (1.f/128.f);
    float rs = rsqrtf(s2 * (1.f/128.f) - mu*mu + 1e-5f);

    float n0 = (v.x - mu) * rs * gv.x + bv.x;
    float n1 = (v.y - mu) * rs * gv.y + bv.y;
    float n2 = (v.z - mu) * rs * gv.z + bv.z;
    float n3 = (v.w - mu) * rs * gv.w + bv.w;

    uint2 o2 = make_uint2(packbf(n0, n1), packbf(n2, n3));
    *(uint2*)&g_zln[row*64 + lane*2] = o2;
}

// ---------------------------------------------------------------------------
// Kernel 1: persistent projections + gating, bf16 tensor cores.
// (R14 pass, unchanged: W n-major [128][68], W frags via ldmatrix.x4.)
// ---------------------------------------------------------------------------
extern "C" __global__ void __launch_bounds__(512)
proj_kernel(const float* __restrict__ mask,
            const float* __restrict__ Wlr, const float* __restrict__ blr,
            const float* __restrict__ Wg,  const float* __restrict__ bg,
            const float* __restrict__ Wog, const float* __restrict__ bog)
{
    extern __shared__ unsigned smu[];
    unsigned* W1 = smu;                 // [128 n][68 kp]
    unsigned* W2 = W1 + 128*68;         // [128 n][68 kp]
    unsigned* As = W2 + 128*68;         // [2][64 row][68 kp]
    float* bb1 = (float*)(As + 2*64*68);
    float* bb2 = bb1 + 128;

    const int t = threadIdx.x, bx = blockIdx.x;
    int cg, ms, stride;
    if      (bx < 120) { cg = 0; ms = bx;       stride = 120; }
    else if (bx < 240) { cg = 1; ms = bx - 120; stride = 120; }
    else               { cg = 2; ms = bx - 240; stride = 60;  }
    const bool dual = (cg < 2);

    if (dual) {
        int cb = cg * 128;
        for (int idx = t; idx < 64*128; idx += 512) {
            int kp = idx >> 7, j = idx & 127;
            W1[j*68 + kp] = packbf(Wlr[(2*kp)*256 + cb + j], Wlr[(2*kp+1)*256 + cb + j]);
            W2[j*68 + kp] = packbf(Wg [(2*kp)*256 + cb + j], Wg [(2*kp+1)*256 + cb + j]);
        }
        if (t < 128) { bb1[t] = blr[cg*128 + t]; bb2[t] = bg[cg*128 + t]; }
    } else {
        for (int idx = t; idx < 64*128; idx += 512) {
            int kp = idx >> 7, j = idx & 127;
            W1[j*68 + kp] = packbf(Wog[(2*kp)*128 + j], Wog[(2*kp+1)*128 + j]);
        }
        if (t < 128) bb1[t] = bog[t];
    }

    const int lane = t & 31, w = t >> 5;
    const int wm = w & 1, wn = w >> 1;      // 2 m-warps x 8 n-warps
    const int tig = lane & 3, grp = lane >> 2;

    const unsigned sAs = (unsigned)__cvta_generic_to_shared(As);
    const int rla = lane & 15;
    const int kca = (lane >> 4) * 4;
    const unsigned aoff0 = ((wm*32 + 0*16 + rla)*68 + kca) * 4;
    const unsigned aoff1 = ((wm*32 + 1*16 + rla)*68 + kca) * 4;
    const unsigned bufstride = 64*68*4;

    const unsigned sW1 = (unsigned)__cvta_generic_to_shared(W1);
    const unsigned sW2 = (unsigned)__cvta_generic_to_shared(W2);
    const int rlw = (lane & 7) + ((lane >> 4) << 3);
    const int kcw = ((lane >> 3) & 1) * 4;
    const unsigned woff = ((wn*16 + rlw)*68 + kcw) * 4;

    __nv_bfloat16* dstb = (cg == 0) ? g_leftb : g_rightb;

    int tile = ms;
    {
        int m0 = tile * 64;
        #pragma unroll
        for (int i = 0; i < 2; ++i) {
            int idx = t + 512*i;
            int r = idx >> 4, kq = idx & 15;
            cp16(As + r*68 + kq*4, g_zln + (size_t)(m0 + r)*64 + kq*4);
        }
        cp_commit();
    }
    int buf = 0;

    for (; tile < 4096; tile += stride) {
        int nxt = tile + stride;
        if (nxt < 4096) {
            int m0 = nxt * 64;
            unsigned* db = As + (buf^1)*64*68;
            #pragma unroll
            for (int i = 0; i < 2; ++i) {
                int idx = t + 512*i;
                int r = idx >> 4, kq = idx & 15;
                cp16(db + r*68 + kq*4, g_zln + (size_t)(m0 + r)*64 + kq*4);
            }
            cp_commit();
            cp_wait<1>();
        } else {
            cp_wait<0>();
        }
        __syncthreads();

        const unsigned abase = sAs + buf*bufstride;
        const int rb = tile * 64;

        float mpre[2][2];
        if (dual) {
            #pragma unroll
            for (int mt = 0; mt < 2; ++mt)
                #pragma unroll
                for (int h = 0; h < 2; ++h)
                    mpre[mt][h] = __ldg(&mask[rb + wm*32 + mt*16 + grp + h*8]);
        }

        float acc1[2][2][4], acc2[2][2][4];
        #pragma unroll
        for (int mt = 0; mt < 2; ++mt)
            #pragma unroll
            for (int nt = 0; nt < 2; ++nt)
                #pragma unroll
                for (int q = 0; q < 4; ++q) { acc1[mt][nt][q] = 0.f; acc2[mt][nt][q] = 0.f; }

        #pragma unroll
        for (int kp0 = 0; kp0 < 64; kp0 += 8) {
            unsigned af[2][4];
            ldsm_x4(af[0][0], af[0][1], af[0][2], af[0][3], abase + aoff0 + kp0*4);
            ldsm_x4(af[1][0], af[1][1], af[1][2], af[1][3], abase + aoff1 + kp0*4);
            unsigned bw1[4];
            ldsm_x4(bw1[0], bw1[1], bw1[2], bw1[3], sW1 + woff + kp0*4);
            if (dual) {
                unsigned bw2[4];
                ldsm_x4(bw2[0], bw2[1], bw2[2], bw2[3], sW2 + woff + kp0*4);
                mma_bf16(acc1[0][0], af[0][0], af[0][1], af[0][2], af[0][3], bw1[0], bw1[1]);
                mma_bf16(acc1[1][0], af[1][0], af[1][1], af[1][2], af[1][3], bw1[0], bw1[1]);
                mma_bf16(acc1[0][1], af[0][0], af[0][1], af[0][2], af[0][3], bw1[2], bw1[3]);
                mma_bf16(acc1[1][1], af[1][0], af[1][1], af[1][2], af[1][3], bw1[2], bw1[3]);
                mma_bf16(acc2[0][0], af[0][0], af[0][1], af[0][2], af[0][3], bw2[0], bw2[1]);
                mma_bf16(acc2[1][0], af[1][0], af[1][1], af[1][2], af[1][3], bw2[0], bw2[1]);
                mma_bf16(acc2[0][1], af[0][0], af[0][1], af[0][2], af[0][3], bw2[2], bw2[3]);
                mma_bf16(acc2[1][1], af[1][0], af[1][1], af[1][2], af[1][3], bw2[2], bw2[3]);
            } else {
                mma_bf16(acc1[0][0], af[0][0], af[0][1], af[0][2], af[0][3], bw1[0], bw1[1]);
                mma_bf16(acc1[1][0], af[1][0], af[1][1], af[1][2], af[1][3], bw1[0], bw1[1]);
                mma_bf16(acc1[0][1], af[0][0], af[0][1], af[0][2], af[0][3], bw1[2], bw1[3]);
                mma_bf16(acc1[1][1], af[1][0], af[1][1], af[1][2], af[1][3], bw1[2], bw1[3]);
            }
        }

        #pragma unroll
        for (int mt = 0; mt < 2; ++mt) {
            #pragma unroll
            for (int nt = 0; nt < 2; ++nt) {
                #pragma unroll
                for (int q = 0; q < 4; ++q) {
                    int r  = wm*32 + mt*16 + grp + ((q >= 2) ? 8 : 0);
                    int oc = wn*16 + nt*8 + tig*2 + (q & 1);
                    if (dual) {
                        float lrv = acc1[mt][nt][q] + bb1[oc];
                        float gtv = acc2[mt][nt][q] + bb2[oc];
                        dstb[(size_t)oc*MROWS + rb + r] =
                            __float2bfloat16(lrv * mpre[mt][q >= 2] * sigmoidf_(gtv));
                    } else {
                        g_gate[(size_t)oc*MROWS + rb + r] =
                            sigmoidf_(acc1[mt][nt][q] + bb1[oc]);
                    }
                }
            }
        }
        __syncthreads();
        buf ^= 1;
    }
}

// ---------------------------------------------------------------------------
// Kernel 2: p[c] = L_c @ R_c^T via bf16 mma, cp.async 2-stage BK=32, ldmatrix.
// (Byte-identical to the R10/R14 pass.)
// ---------------------------------------------------------------------------
extern "C" __global__ void __launch_bounds__(256, 2)
einsum_kernel()
{
    __shared__ unsigned As[2][128][20];
    __shared__ unsigned Bs[2][128][20];

    const int t = threadIdx.x;
    const int lane = t & 31;
    const int w = t >> 5;
    const int wm = w & 3;
    const int wn = w >> 2;
    const int jbase = blockIdx.x * 128;
    const int ibase = blockIdx.y * 128;
    const int c = blockIdx.z;

    const __nv_bfloat16* A = g_leftb  + (size_t)c*MROWS + (size_t)ibase*512;
    const __nv_bfloat16* B = g_rightb + (size_t)c*MROWS + (size_t)jbase*512;

    const int tig = lane & 3;
    const int grp = lane >> 2;

    const unsigned sAs = (unsigned)__cvta_generic_to_shared(As);
    const unsigned sBs = (unsigned)__cvta_generic_to_shared(Bs);
    const int rla = lane & 15;
    const int kca = (lane >> 4) * 4;
    const int rlb = (lane & 7) + ((lane >> 4) << 3);
    const int kcb = ((lane >> 3) & 1) * 4;
    unsigned aoff[2], boff[4];
    #pragma unroll
    for (int mt = 0; mt < 2; ++mt)
        aoff[mt] = ((wm*32 + mt*16 + rla)*20 + kca) * 4;
    #pragma unroll
    for (int ntp = 0; ntp < 4; ++ntp)
        boff[ntp] = ((wn*64 + ntp*16 + rlb)*20 + kcb) * 4;
    const unsigned ststride = 128*20*4;

    float acc[2][8][4];
    #pragma unroll
    for (int mt = 0; mt < 2; ++mt)
        #pragma unroll
        for (int nt = 0; nt < 8; ++nt)
            #pragma unroll
            for (int q = 0; q < 4; ++q) acc[mt][nt][q] = 0.f;

    #pragma unroll
    for (int st = 0; st < 2; ++st) {
        int k0 = st * 32;
        #pragma unroll
        for (int i = 0; i < 2; ++i) {
            int idx = t + 256*i;
            int row = idx >> 2, q = idx & 3;
            cp16(&As[st][row][q*4], A + row*512 + k0 + q*8);
            cp16(&Bs[st][row][q*4], B + row*512 + k0 + q*8);
        }
        cp_commit();
    }

    int it = 0;
    for (int k0 = 0; k0 < 512; k0 += 32, it ^= 1) {
        if (k0 + 32 >= 512) cp_wait<0>(); else cp_wait<1>();
        __syncthreads();

        const unsigned ab = sAs + it*ststride;
        const unsigned bb = sBs + it*ststride;

        #pragma unroll
        for (int kk = 0; kk < 2; ++kk) {
            unsigned af[2][4], bf[8][2];
            ldsm_x4(af[0][0], af[0][1], af[0][2], af[0][3], ab + aoff[0] + kk*32);
            ldsm_x4(af[1][0], af[1][1], af[1][2], af[1][3], ab + aoff[1] + kk*32);
            #pragma unroll
            for (int ntp = 0; ntp < 4; ++ntp)
                ldsm_x4(bf[ntp*2][0], bf[ntp*2][1], bf[ntp*2+1][0], bf[ntp*2+1][1],
                        bb + boff[ntp] + kk*32);
            #pragma unroll
            for (int mt = 0; mt < 2; ++mt)
                #pragma unroll
                for (int nt = 0; nt < 8; ++nt)
                    mma_bf16(acc[mt][nt], af[mt][0], af[mt][1], af[mt][2], af[mt][3],
                             bf[nt][0], bf[nt][1]);
        }

        if (k0 + 64 < 512) {
            __syncthreads();
            int kn = k0 + 64;
            #pragma unroll
            for (int i = 0; i < 2; ++i) {
                int idx = t + 256*i;
                int row = idx >> 2, q = idx & 3;
                cp16(&As[it][row][q*4], A + row*512 + kn + q*8);
                cp16(&Bs[it][row][q*4], B + row*512 + kn + q*8);
            }
            cp_commit();
        }
    }

    unsigned* Pb = g_pb + (size_t)c*(MROWS/2);
    #pragma unroll
    for (int mt = 0; mt < 2; ++mt) {
        int i0 = ibase + wm*32 + mt*16 + grp;
        #pragma unroll
        for (int nt = 0; nt < 8; ++nt) {
            int j0 = jbase + wn*64 + nt*8 + tig*2;
            Pb[(size_t)i0*256 + (j0 >> 1)]     = packbf(acc[mt][nt][0], acc[mt][nt][1]);
            Pb[(size_t)(i0+8)*256 + (j0 >> 1)] = packbf(acc[mt][nt][2], acc[mt][nt][3]);
        }
    }
}

// ---------------------------------------------------------------------------
// Kernel 3: PERSISTENT LN2 + (pln @ W_op, bf16 mma) + gate + residual.
// 512 thr, grid 304 (2 blocks/SM, ~95 KB). LN2 output packed to bf16 A-operand
// [64 r][68 cp]; W_op bf16 resident [128 d][68 cp]; ldmatrix both operands
// (verified proj patterns). P tiles double-buffered via cp.async.
// ---------------------------------------------------------------------------
extern "C" __global__ void __launch_bounds__(512, 2)
final_kernel(const float* __restrict__ Z,
             const float* __restrict__ g2v, const float* __restrict__ b2v,
             const float* __restrict__ obias, float* __restrict__ out)
{
    extern __shared__ unsigned smu[];
    unsigned* Ws  = smu;                  // [128 d][68 cp] bf16 pairs
    unsigned* Pp0 = Ws + 128*68;          // [128 c][36] packed bf16 r-pairs
    unsigned* Pp1 = Pp0 + 128*36;
    unsigned* Ab  = Pp1 + 128*36;         // [64 r][68 cp] bf16 c-pairs (LN2 out)
    float* ps1 = (float*)(Ab + 64*68);    // [8][64]
    float* ps2 = ps1 + 8*64;
    float* g2s = ps2 + 8*64;              // 128
    float* b2s = g2s + 128;
    float* obs = b2s + 128;
    float* mus = obs + 128;               // 64
    float* rss = mus + 64;                // 64

    const int t = threadIdx.x;

    // prologue: W_op (bf16 packed) + first P tile in one group
    #pragma unroll
    for (int i = 0; i < 4; ++i) {
        int idx = t + 512*i;              // 0..2047
        int d = idx >> 4, seg = idx & 15;
        cp16(Ws + d*68 + seg*4, g_wopb + d*64 + seg*4);
    }
    {
        int rb0 = blockIdx.x * 64;
        #pragma unroll
        for (int i = 0; i < 2; ++i) {
            int idx = t + 512*i;          // 0..1023
            int c = idx >> 3, seg = idx & 7;
            cp16(Pp0 + c*36 + seg*4, g_pb + (size_t)c*(MROWS/2) + (rb0 >> 1) + seg*4);
        }
    }
    cp_commit();
    if (t < 128) { g2s[t] = g2v[t]; b2s[t] = b2v[t]; obs[t] = obias[t]; }

    const int lane = t & 31, w = t >> 5;
    const int wm = w & 1, wn = w >> 1;    // 2 m-warps x 8 n-warps (proj layout)
    const int tig = lane & 3, grp = lane >> 2;

    // ldmatrix maps (proj-verified)
    const unsigned sAb = (unsigned)__cvta_generic_to_shared(Ab);
    const int rla = lane & 15;
    const int kca = (lane >> 4) * 4;
    const unsigned aoff0 = ((wm*32 + 0*16 + rla)*68 + kca) * 4;
    const unsigned aoff1 = ((wm*32 + 1*16 + rla)*68 + kca) * 4;
    const unsigned sWs = (unsigned)__cvta_generic_to_shared(Ws);
    const int rlw = (lane & 7) + ((lane >> 4) << 3);
    const int kcw = ((lane >> 3) & 1) * 4;
    const unsigned woff = ((wn*16 + rlw)*68 + kcw) * 4;

    int st = 0;
    for (int tile = blockIdx.x; tile < 4096; tile += 304, st ^= 1) {
        unsigned* Pp = st ? Pp1 : Pp0;
        const int rb = tile * 64;

        cp_wait<0>();
        __syncthreads();

        // prefetch NEXT tile's packed P into the other stage
        int ntile = tile + 304;
        if (ntile < 4096) {
            unsigned* D = st ? Pp0 : Pp1;
            int rbn = ntile * 64;
            #pragma unroll
            for (int i = 0; i < 2; ++i) {
                int idx = t + 512*i;
                int c = idx >> 3, seg = idx & 7;
                cp16(D + c*36 + seg*4, g_pb + (size_t)c*(MROWS/2) + (rbn >> 1) + seg*4);
            }
            cp_commit();
        }

        // LN partials over c (8 groups of 16 c's, lanes sweep rows)
        {
            int h = t >> 6, r = t & 63;
            int r2 = r >> 1, hi = r & 1;
            float s = 0.f, s2 = 0.f;
            #pragma unroll
            for (int cc = 0; cc < 16; ++cc) {
                unsigned pk = Pp[(h*16 + cc)*36 + r2];
                __nv_bfloat162 h2 = *reinterpret_cast<const __nv_bfloat162*>(&pk);
                float v = hi ? __bfloat162float(h2.y) : __bfloat162float(h2.x);
                s += v; s2 += v*v;
            }
            ps1[h*64 + r] = s; ps2[h*64 + r] = s2;
        }
        __syncthreads();
        if (t < 64) {
            float s = 0.f, s2 = 0.f;
            #pragma unroll
            for (int h = 0; h < 8; ++h) { s += ps1[h*64 + t]; s2 += ps2[h*64 + t]; }
            float mu = s * (1.f/128.f);
            float var = s2 * (1.f/128.f) - mu*mu;
            mus[t] = mu; rss[t] = rsqrtf(var + 1e-5f);
        }
        __syncthreads();

        // Expand: LN2 + pack as bf16 c-pairs -> Ab[r][cp].
        // Task (cp, r2): reads Pp[2cp][r2], Pp[2cp+1][r2]; writes Ab rows 2r2, 2r2+1.
        #pragma unroll
        for (int i = 0; i < 4; ++i) {
            int idx = t + 512*i;          // 0..2047
            int cp = idx >> 5, r2 = idx & 31;
            int c0 = 2*cp, c1 = 2*cp + 1;
            unsigned pk0 = Pp[c0*36 + r2];
            unsigned pk1 = Pp[c1*36 + r2];
            __nv_bfloat162 h0 = *reinterpret_cast<const __nv_bfloat162*>(&pk0);
            __nv_bfloat162 h1 = *reinterpret_cast<const __nv_bfloat162*>(&pk1);
            int r = 2*r2;
            float m0 = mus[r], q0 = rss[r], m1 = mus[r+1], q1 = rss[r+1];
            float g0 = g2s[c0], bb0 = b2s[c0], g1 = g2s[c1], bb1 = b2s[c1];
            float a00 = (__bfloat162float(h0.x) - m0) * q0 * g0 + bb0;   // c0, r
            float a01 = (__bfloat162float(h0.y) - m1) * q1 * g0 + bb0;   // c0, r+1
            float a10 = (__bfloat162float(h1.x) - m0) * q0 * g1 + bb1;   // c1, r
            float a11 = (__bfloat162float(h1.y) - m1) * q1 * g1 + bb1;   // c1, r+1
            Ab[ r   *68 + cp] = packbf(a00, a10);
            Ab[(r+1)*68 + cp] = packbf(a01, a11);
        }
        __syncthreads();

        // prefetch gate + Z (latency hidden under GEMM)
        float  gpre[2][2][4];
        float2 zpre[2][2][2];
        #pragma unroll
        for (int mt = 0; mt < 2; ++mt) {
            int r0 = wm*32 + mt*16 + grp;
            #pragma unroll
            for (int nt = 0; nt < 2; ++nt) {
                int d0 = wn*16 + nt*8 + tig*2;
                #pragma unroll
                for (int q = 0; q < 4; ++q) {
                    int r = r0 + ((q >= 2) ? 8 : 0);
                    gpre[mt][nt][q] = __ldg(&g_gate[(size_t)(d0 + (q & 1))*MROWS + rb + r]);
                }
                zpre[mt][nt][0] = *(const float2*)&Z[(size_t)(rb + r0    )*128 + d0];
                zpre[mt][nt][1] = *(const float2*)&Z[(size_t)(rb + r0 + 8)*128 + d0];
            }
        }

        // GEMM: M=64(r), N=128(d), K=128(c) in bf16 (proj non-dual structure)
        float acc[2][2][4];
        #pragma unroll
        for (int mt = 0; mt < 2; ++mt)
            #pragma unroll
            for (int nt = 0; nt < 2; ++nt)
                #pragma unroll
                for (int q = 0; q < 4; ++q) acc[mt][nt][q] = 0.f;

        #pragma unroll
        for (int kp0 = 0; kp0 < 64; kp0 += 8) {
            unsigned af[2][4];
            ldsm_x4(af[0][0], af[0][1], af[0][2], af[0][3], sAb + aoff0 + kp0*4);
            ldsm_x4(af[1][0], af[1][1], af[1][2], af[1][3], sAb + aoff1 + kp0*4);
            unsigned bw[4];
            ldsm_x4(bw[0], bw[1], bw[2], bw[3], sWs + woff + kp0*4);
            mma_bf16(acc[0][0], af[0][0], af[0][1], af[0][2], af[0][3], bw[0], bw[1]);
            mma_bf16(acc[1][0], af[1][0], af[1][1], af[1][2], af[1][3], bw[0], bw[1]);
            mma_bf16(acc[0][1], af[0][0], af[0][1], af[0][2], af[0][3], bw[2], bw[3]);
            mma_bf16(acc[1][1], af[1][0], af[1][1], af[1][2], af[1][3], bw[2], bw[3]);
        }

        // epilogue: direct gated-residual float2 stores (sector-aligned)
        #pragma unroll
        for (int mt = 0; mt < 2; ++mt) {
            int r0 = wm*32 + mt*16 + grp;
            #pragma unroll
            for (int nt = 0; nt < 2; ++nt) {
                int d0 = wn*16 + nt*8 + tig*2;
                float ob0 = obs[d0], ob1 = obs[d0 + 1];
                float2 o0, o1;
                o0.x = zpre[mt][nt][0].x + gpre[mt][nt][0] * (acc[mt][nt][0] + ob0);
                o0.y = zpre[mt][nt][0].y + gpre[mt][nt][1] * (acc[mt][nt][1] + ob1);
                o1.x = zpre[mt][nt][1].x + gpre[mt][nt][2] * (acc[mt][nt][2] + ob0);
                o1.y = zpre[mt][nt][1].y + gpre[mt][nt][3] * (acc[mt][nt][3] + ob1);
                *(float2*)&out[(size_t)(rb + r0    )*128 + d0] = o0;
                *(float2*)&out[(size_t)(rb + r0 + 8)*128 + d0] = o1;
            }
        }
        // next iteration's cp_wait + __syncthreads protects buffer reuse
    }
}

// ---------------------------------------------------------------------------
extern "C" void kernel_launch(void* const* d_in, const int* in_sizes, int n_in,
                              void* d_out, int out_size)
{
    const float* Zr   = (const float*)d_in[0];
    const float* mask = (const float*)d_in[1];
    const float* g1   = (const float*)d_in[2];
    const float* b1   = (const float*)d_in[3];
    const float* Wlr  = (const float*)d_in[4];
    const float* blr  = (const float*)d_in[5];
    const float* Wg   = (const float*)d_in[6];
    const float* bg   = (const float*)d_in[7];
    const float* Wog  = (const float*)d_in[8];
    const float* bog  = (const float*)d_in[9];
    const float* g2   = (const float*)d_in[10];
    const float* b2   = (const float*)d_in[11];
    const float* Wop  = (const float*)d_in[12];
    const float* ob   = (const float*)d_in[13];
    float* out = (float*)d_out;

    const size_t sm1 = (size_t)(2*128*68 + 2*64*68 + 256) * 4;                       // ~105.5 KB
    const size_t sm3 = (size_t)(128*68 + 2*128*36 + 64*68 + 16*64 + 3*128 + 2*64)*4; // ~95.2 KB
    cudaFuncSetAttribute(proj_kernel,  cudaFuncAttributeMaxDynamicSharedMemorySize, (int)sm1);
    cudaFuncSetAttribute(final_kernel, cudaFuncAttributeMaxDynamicSharedMemorySize, (int)sm3);

    ln1_kernel<<<32768, 256>>>(Zr, g1, b1, Wop);
    proj_kernel<<<300, 512, sm1>>>(mask, Wlr, blr, Wg, bg, Wog, bog);
    einsum_kernel<<<dim3(4, 4, 128), 256>>>();
    final_kernel<<<304, 512, sm3>>>(Zr, g2, b2, ob, out);
}